// round 3
// baseline (speedup 1.0000x reference)
#include <cuda_runtime.h>
#include <math.h>

// Problem constants
#define BATCH 32
#define DDIM  512
#define CDIM  256
#define NDIM  1024
#define SS    32

// ---------------- scratch (device globals; no allocation allowed) ----------------
__device__ float g_x1[(size_t)BATCH * CDIM * NDIM];            // 32 MB  [b][c][n]
__device__ float g_qkve[(size_t)BATCH * 4 * CDIM * NDIM];      // 128 MB [b][m:1024][n]  rows: q(0..255) k(256..511) v(512..767) e(768..1023)
__device__ float g_logits[(size_t)BATCH * NDIM * NDIM];        // 128 MB [b][i][j]
__device__ float g_out[(size_t)BATCH * CDIM * NDIM];           // 32 MB  [b][c][i]
__device__ float g_pos[(size_t)CDIM * NDIM];                   // 1 MB   [c][n]
__device__ float g_wqkve[(size_t)4 * CDIM * CDIM];             // 1 MB   [m:1024][c:256]
__device__ float g_bqkve[4 * CDIM];

// ---------------- prep: pos table + stacked qkve weights/bias ----------------
__global__ void prep_kernel(const float* __restrict__ qw, const float* __restrict__ kw,
                            const float* __restrict__ vw, const float* __restrict__ ew,
                            const float* __restrict__ qb, const float* __restrict__ kb,
                            const float* __restrict__ vb, const float* __restrict__ eb,
                            const float* __restrict__ rel_h, const float* __restrict__ rel_w) {
    int t = blockIdx.x * blockDim.x + threadIdx.x;   // 262144 threads
    // pos[c][n] = rel_h[c][h] + rel_w[c][w], n = h*32+w
    {
        int c = t >> 10, n = t & 1023;
        int h = n >> 5, w = n & 31;
        g_pos[t] = rel_h[c * SS + h] + rel_w[c * SS + w];
    }
    // stacked weight [1024][256]
    {
        int m = t >> 8, c = t & 255;
        int sel = m >> 8, mr = m & 255;
        const float* src = (sel == 0) ? qw : (sel == 1) ? kw : (sel == 2) ? vw : ew;
        g_wqkve[t] = src[mr * CDIM + c];
    }
    if (t < 4 * CDIM) {
        int sel = t >> 8, mr = t & 255;
        const float* src = (sel == 0) ? qb : (sel == 1) ? kb : (sel == 2) ? vb : eb;
        g_bqkve[t] = src[mr];
    }
}

// ---------------- NN GEMM: C[b][m][n] = sum_k A[m][k] * B[b][k][n], fused epilogues ----------------
// MODE 0: cv1   (K=512, M=256)  C = g_x1,  epi: silu(scale*acc+beta)
// MODE 1: qkve  (K=256, M=1024) A = g_wqkve, B = g_x1, C = g_qkve, epi: +bias
// MODE 2: cv2   (K=256, M=512)  B = g_out, epi: resid + silu(scale*acc+beta)
template <int MODE>
__global__ void __launch_bounds__(256)
gemm_nn(const float* __restrict__ Aext, const float* __restrict__ Bext,
        float* __restrict__ Cext, const float* __restrict__ p0,
        const float* __restrict__ p1, const float* __restrict__ resid) {
    constexpr int KD = (MODE == 0) ? 512 : 256;
    constexpr int MD = (MODE == 0) ? 256 : (MODE == 1) ? 1024 : 512;

    const float* A    = (MODE == 1) ? g_wqkve : Aext;
    const float* Ball = (MODE == 0) ? Bext : (MODE == 1) ? g_x1 : g_out;
    float*       Call = (MODE == 0) ? g_x1 : (MODE == 1) ? g_qkve : Cext;

    const int b  = blockIdx.z;
    const int m0 = blockIdx.y * 64;
    const int n0 = blockIdx.x * 64;
    const float* Bb = Ball + (size_t)b * KD * NDIM;
    float*       Cb = Call + (size_t)b * MD * NDIM;

    __shared__ float As[64][16];   // [m][k]
    __shared__ float Bs[16][64];   // [k][n]

    const int tid = threadIdx.x;
    const int tx = tid & 15, ty = tid >> 4;
    const int am = tid >> 2, ak = (tid & 3) * 4;
    const int bk = tid >> 4, bn = (tid & 15) * 4;

    float acc[4][4] = {};

    for (int k0 = 0; k0 < KD; k0 += 16) {
        float4 av = *reinterpret_cast<const float4*>(&A[(size_t)(m0 + am) * KD + k0 + ak]);
        *reinterpret_cast<float4*>(&As[am][ak]) = av;
        float4 bv = *reinterpret_cast<const float4*>(&Bb[(size_t)(k0 + bk) * NDIM + n0 + bn]);
        *reinterpret_cast<float4*>(&Bs[bk][bn]) = bv;
        __syncthreads();
#pragma unroll
        for (int kk = 0; kk < 16; ++kk) {
            float a[4];
#pragma unroll
            for (int i = 0; i < 4; i++) a[i] = As[ty * 4 + i][kk];
            float4 bb = *reinterpret_cast<const float4*>(&Bs[kk][tx * 4]);
            float bj[4] = {bb.x, bb.y, bb.z, bb.w};
#pragma unroll
            for (int i = 0; i < 4; i++)
#pragma unroll
                for (int j = 0; j < 4; j++) acc[i][j] = fmaf(a[i], bj[j], acc[i][j]);
        }
        __syncthreads();
    }

    const float* bias = (MODE == 1) ? g_bqkve : p0;
#pragma unroll
    for (int i = 0; i < 4; i++) {
        int m = m0 + ty * 4 + i;
        float sc = 0.f, bt = 0.f, bi = 0.f;
        if (MODE == 1) bi = bias[m];
        else { sc = p0[m] * rsqrtf(1.0f + 1e-5f); bt = p1[m]; }
#pragma unroll
        for (int j = 0; j < 4; j++) {
            int n = n0 + tx * 4 + j;
            size_t idx = (size_t)m * NDIM + n;
            float v = acc[i][j];
            if (MODE == 1) {
                Cb[idx] = v + bi;
            } else {
                float t = v * sc + bt;
                float s = t / (1.0f + expf(-t));
                if (MODE == 2) s += resid[(size_t)b * MD * NDIM + idx];
                Cb[idx] = s;
            }
        }
    }
}

// ---------------- logits: [b][i][j] = sum_{k<256} q[k][i]k[k][j] + sum pos[k][i]e[k][j] ----------------
__global__ void __launch_bounds__(256)
gemm_logits() {
    const int b  = blockIdx.z;
    const int i0 = blockIdx.y * 64;
    const int j0 = blockIdx.x * 64;
    const float* base = g_qkve + (size_t)b * 4 * CDIM * NDIM;

    __shared__ float As[16][64];   // [k][i]
    __shared__ float Bs[16][64];   // [k][j]

    const int tid = threadIdx.x;
    const int tx = tid & 15, ty = tid >> 4;
    const int lk = tid >> 4, lm = (tid & 15) * 4;

    float acc[4][4] = {};

    for (int k0 = 0; k0 < 512; k0 += 16) {
        const float* Arow;
        const float* Brow;
        if (k0 < 256) {
            Arow = base + (size_t)k0 * NDIM;                 // q rows
            Brow = base + (size_t)(256 + k0) * NDIM;         // k rows
        } else {
            Arow = g_pos + (size_t)(k0 - 256) * NDIM;        // pos rows (batch-indep)
            Brow = base + (size_t)(768 + (k0 - 256)) * NDIM; // e rows
        }
        float4 av = *reinterpret_cast<const float4*>(&Arow[(size_t)lk * NDIM + i0 + lm]);
        *reinterpret_cast<float4*>(&As[lk][lm]) = av;
        float4 bv = *reinterpret_cast<const float4*>(&Brow[(size_t)lk * NDIM + j0 + lm]);
        *reinterpret_cast<float4*>(&Bs[lk][lm]) = bv;
        __syncthreads();
#pragma unroll
        for (int kk = 0; kk < 16; ++kk) {
            float4 aa = *reinterpret_cast<const float4*>(&As[kk][ty * 4]);
            float4 bb = *reinterpret_cast<const float4*>(&Bs[kk][tx * 4]);
            float ai[4] = {aa.x, aa.y, aa.z, aa.w};
            float bj[4] = {bb.x, bb.y, bb.z, bb.w};
#pragma unroll
            for (int i = 0; i < 4; i++)
#pragma unroll
                for (int j = 0; j < 4; j++) acc[i][j] = fmaf(ai[i], bj[j], acc[i][j]);
        }
        __syncthreads();
    }

    float* L = g_logits + (size_t)b * NDIM * NDIM;
#pragma unroll
    for (int i = 0; i < 4; i++)
#pragma unroll
        for (int j = 0; j < 4; j++)
            L[(size_t)(i0 + ty * 4 + i) * NDIM + j0 + tx * 4 + j] = acc[i][j];
}

// ---------------- softmax over j (rows of 1024), in place ----------------
__global__ void __launch_bounds__(256)
softmax_kernel() {
    float* p = g_logits + (size_t)blockIdx.x * NDIM;
    const int tid = threadIdx.x;
    __shared__ float red[8];

    float4 v = *reinterpret_cast<const float4*>(&p[tid * 4]);
    float m = fmaxf(fmaxf(v.x, v.y), fmaxf(v.z, v.w));
#pragma unroll
    for (int o = 16; o; o >>= 1) m = fmaxf(m, __shfl_xor_sync(0xffffffffu, m, o));
    if ((tid & 31) == 0) red[tid >> 5] = m;
    __syncthreads();
    m = red[0];
#pragma unroll
    for (int r = 1; r < 8; r++) m = fmaxf(m, red[r]);
    __syncthreads();

    float e0 = __expf(v.x - m), e1 = __expf(v.y - m), e2 = __expf(v.z - m), e3 = __expf(v.w - m);
    float s = (e0 + e1) + (e2 + e3);
#pragma unroll
    for (int o = 16; o; o >>= 1) s += __shfl_xor_sync(0xffffffffu, s, o);
    if ((tid & 31) == 0) red[tid >> 5] = s;
    __syncthreads();
    s = ((red[0] + red[1]) + (red[2] + red[3])) + ((red[4] + red[5]) + (red[6] + red[7]));
    float inv = 1.0f / s;
    float4 o4 = make_float4(e0 * inv, e1 * inv, e2 * inv, e3 * inv);
    *reinterpret_cast<float4*>(&p[tid * 4]) = o4;
}

// ---------------- out[b][c][i] = sum_j V[b][c][j] * attn[b][i][j]  (NT) ----------------
__global__ void __launch_bounds__(256)
gemm_out() {
    const int b  = blockIdx.z;
    const int c0 = blockIdx.y * 64;
    const int i0 = blockIdx.x * 64;
    const float* V  = g_qkve + (size_t)b * 4 * CDIM * NDIM + (size_t)512 * NDIM;
    const float* Ab = g_logits + (size_t)b * NDIM * NDIM;
    float*       Ob = g_out + (size_t)b * CDIM * NDIM;

    __shared__ float As[64][16];     // [c][k]
    __shared__ float Bs[16][66];     // [k][i], width 66 -> conflict-free transposed store

    const int tid = threadIdx.x;
    const int tx = tid & 15, ty = tid >> 4;
    const int am = tid >> 2, ak = (tid & 3) * 4;   // same mapping for both tiles

    float acc[4][4] = {};

    for (int k0 = 0; k0 < NDIM; k0 += 16) {
        float4 av = *reinterpret_cast<const float4*>(&V[(size_t)(c0 + am) * NDIM + k0 + ak]);
        *reinterpret_cast<float4*>(&As[am][ak]) = av;
        float4 bv = *reinterpret_cast<const float4*>(&Ab[(size_t)(i0 + am) * NDIM + k0 + ak]);
        Bs[ak + 0][am] = bv.x; Bs[ak + 1][am] = bv.y; Bs[ak + 2][am] = bv.z; Bs[ak + 3][am] = bv.w;
        __syncthreads();
#pragma unroll
        for (int kk = 0; kk < 16; ++kk) {
            float a[4];
#pragma unroll
            for (int i = 0; i < 4; i++) a[i] = As[ty * 4 + i][kk];
#pragma unroll
            for (int j = 0; j < 4; j++) {
                float bj = Bs[kk][tx * 4 + j];
#pragma unroll
                for (int i = 0; i < 4; i++) acc[i][j] = fmaf(a[i], bj, acc[i][j]);
            }
        }
        __syncthreads();
    }

#pragma unroll
    for (int i = 0; i < 4; i++)
#pragma unroll
        for (int j = 0; j < 4; j++)
            Ob[(size_t)(c0 + ty * 4 + i) * NDIM + i0 + tx * 4 + j] = acc[i][j];
}

// ---------------- launch ----------------
extern "C" void kernel_launch(void* const* d_in, const int* in_sizes, int n_in,
                              void* d_out, int out_size) {
    const float* x      = (const float*)d_in[0];
    const float* cv1_w  = (const float*)d_in[1];
    const float* cv1_g  = (const float*)d_in[2];
    const float* cv1_b  = (const float*)d_in[3];
    const float* q_w    = (const float*)d_in[4];
    const float* q_b    = (const float*)d_in[5];
    const float* k_w    = (const float*)d_in[6];
    const float* k_b    = (const float*)d_in[7];
    const float* v_w    = (const float*)d_in[8];
    const float* v_b    = (const float*)d_in[9];
    const float* e_w    = (const float*)d_in[10];
    const float* e_b    = (const float*)d_in[11];
    const float* rel_h  = (const float*)d_in[12];
    const float* rel_w  = (const float*)d_in[13];
    const float* cv2_w  = (const float*)d_in[14];
    const float* cv2_g  = (const float*)d_in[15];
    const float* cv2_b  = (const float*)d_in[16];
    float* out = (float*)d_out;

    prep_kernel<<<1024, 256>>>(q_w, k_w, v_w, e_w, q_b, k_b, v_b, e_b, rel_h, rel_w);

    // cv1: x1 = silu(bn(W1 @ x))
    gemm_nn<0><<<dim3(16, 4, BATCH), 256>>>(cv1_w, x, nullptr, cv1_g, cv1_b, nullptr);

    // fused q/k/v/e projections
    gemm_nn<1><<<dim3(16, 16, BATCH), 256>>>(nullptr, nullptr, nullptr, nullptr, nullptr, nullptr);

    // logits = [q;pos]^T [k;e]
    gemm_logits<<<dim3(16, 16, BATCH), 256>>>();

    // softmax over last axis
    softmax_kernel<<<BATCH * NDIM, 256>>>();

    // out = V @ attn^T
    gemm_out<<<dim3(16, 4, BATCH), 256>>>();

    // cv2 + residual
    gemm_nn<2><<<dim3(16, 8, BATCH), 256>>>(cv2_w, nullptr, out, cv2_g, cv2_b, x);
}

// round 5
// speedup vs baseline: 3.8773x; 3.8773x over previous
#include <cuda_runtime.h>
#include <cuda_bf16.h>
#include <cstdint>
#include <math.h>

#define BATCH 32

// ================= scratch (device globals) =================
__device__ __align__(256) __nv_bfloat16 g_w1_hi[256*512],  g_w1_lo[256*512];
__device__ __align__(256) __nv_bfloat16 g_wqke_hi[768*256], g_wqke_lo[768*256];
__device__ __align__(256) __nv_bfloat16 g_wv_hi[256*256],  g_wv_lo[256*256];
__device__ __align__(256) __nv_bfloat16 g_w2_hi[512*256],  g_w2_lo[512*256];
__device__ float g_bqke[768];
__device__ float g_bv[256];
__device__ __align__(256) __nv_bfloat16 g_posT_hi[1024*256], g_posT_lo[1024*256];
__device__ __align__(256) __nv_bfloat16 g_xT_hi[(size_t)BATCH*1024*512], g_xT_lo[(size_t)BATCH*1024*512];
__device__ __align__(256) __nv_bfloat16 g_x1T_hi[(size_t)BATCH*1024*256], g_x1T_lo[(size_t)BATCH*1024*256];
__device__ __align__(256) __nv_bfloat16 g_qT_hi[(size_t)BATCH*1024*256], g_qT_lo[(size_t)BATCH*1024*256];
__device__ __align__(256) __nv_bfloat16 g_kT_hi[(size_t)BATCH*1024*256], g_kT_lo[(size_t)BATCH*1024*256];
__device__ __align__(256) __nv_bfloat16 g_eT_hi[(size_t)BATCH*1024*256], g_eT_lo[(size_t)BATCH*1024*256];
__device__ __align__(256) __nv_bfloat16 g_v_hi[(size_t)BATCH*256*1024],  g_v_lo[(size_t)BATCH*256*1024];
__device__ float g_logits[(size_t)BATCH*1024*1024];
__device__ __align__(256) __nv_bfloat16 g_attn_hi[(size_t)BATCH*1024*1024], g_attn_lo[(size_t)BATCH*1024*1024];
__device__ __align__(256) __nv_bfloat16 g_outT_hi[(size_t)BATCH*1024*256], g_outT_lo[(size_t)BATCH*1024*256];

// ================= helpers =================
__device__ __forceinline__ uint32_t smem_u32(const void* p) {
    uint32_t a;
    asm("{ .reg .u64 t; cvta.to.shared.u64 t, %1; cvt.u32.u64 %0, t; }" : "=r"(a) : "l"(p));
    return a;
}
__device__ __forceinline__ void cp16(uint32_t s, const void* g) {
    asm volatile("cp.async.cg.shared.global [%0], [%1], 16;" :: "r"(s), "l"(g) : "memory");
}
#define CP_COMMIT() asm volatile("cp.async.commit_group;" ::: "memory")
#define CP_WAIT0()  asm volatile("cp.async.wait_group 0;" ::: "memory")

__device__ __forceinline__ void ldsm4(uint32_t* r, uint32_t addr) {
    asm volatile("ldmatrix.sync.aligned.m8n8.x4.shared.b16 {%0,%1,%2,%3}, [%4];"
        : "=r"(r[0]), "=r"(r[1]), "=r"(r[2]), "=r"(r[3]) : "r"(addr));
}
__device__ __forceinline__ void mma16816(float* c, const uint32_t* a, const uint32_t* b) {
    asm volatile("mma.sync.aligned.m16n8k16.row.col.f32.bf16.bf16.f32 "
        "{%0,%1,%2,%3}, {%4,%5,%6,%7}, {%8,%9}, {%0,%1,%2,%3};"
        : "+f"(c[0]), "+f"(c[1]), "+f"(c[2]), "+f"(c[3])
        : "r"(a[0]), "r"(a[1]), "r"(a[2]), "r"(a[3]), "r"(b[0]), "r"(b[1]));
}
__device__ __forceinline__ void bsplit(float v, __nv_bfloat16& h, __nv_bfloat16& l) {
    h = __float2bfloat16(v);
    l = __float2bfloat16(v - __bfloat162float(h));
}
__device__ __forceinline__ void split_pair(float v0, float v1, uint32_t& hi2, uint32_t& lo2) {
    __nv_bfloat16 h0, l0, h1, l1;
    bsplit(v0, h0, l0); bsplit(v1, h1, l1);
    __nv_bfloat162 h = __nv_bfloat162(h0, h1), l = __nv_bfloat162(l0, l1);
    hi2 = *reinterpret_cast<uint32_t*>(&h);
    lo2 = *reinterpret_cast<uint32_t*>(&l);
}
__device__ __forceinline__ float silu(float t) { return t / (1.0f + __expf(-t)); }

// ================= prep kernels =================
__global__ void prep_w(const float* __restrict__ w1,
                       const float* __restrict__ qw, const float* __restrict__ kw,
                       const float* __restrict__ vw, const float* __restrict__ ew,
                       const float* __restrict__ qb, const float* __restrict__ kb,
                       const float* __restrict__ vb, const float* __restrict__ eb,
                       const float* __restrict__ w2,
                       const float* __restrict__ rh, const float* __restrict__ rw) {
    int t = blockIdx.x * blockDim.x + threadIdx.x;   // 262144 threads
    if (t < 256*512) bsplit(w1[t], g_w1_hi[t], g_w1_lo[t]);
    if (t < 768*256) {
        int m = t >> 8, c = t & 255, sel = m >> 8, mr = m & 255;
        const float* s = (sel==0)?qw:(sel==1)?kw:ew;
        bsplit(s[mr*256 + c], g_wqke_hi[t], g_wqke_lo[t]);
    }
    if (t < 256*256) bsplit(vw[t], g_wv_hi[t], g_wv_lo[t]);
    if (t < 512*256) bsplit(w2[t], g_w2_hi[t], g_w2_lo[t]);
    if (t < 768) {
        int sel = t >> 8, mr = t & 255;
        g_bqke[t] = ((sel==0)?qb:(sel==1)?kb:eb)[mr];
    }
    if (t < 256) g_bv[t] = vb[t];
    {   // posT[n][c]
        int n = t >> 8, c = t & 255;
        float pv = rh[c*32 + (n>>5)] + rw[c*32 + (n&31)];
        bsplit(pv, g_posT_hi[t], g_posT_lo[t]);
    }
}

// transpose + split x: [b][d][n] fp32 -> xT[b][n][d] bf16 hi/lo
__global__ void xt_conv(const float* __restrict__ x) {
    __shared__ float tile[32][33];
    int b = blockIdx.z, d0 = blockIdx.y*32, n0 = blockIdx.x*32;
    int tx = threadIdx.x, ty = threadIdx.y;  // 32 x 8
    const float* xp = x + ((size_t)b*512 + d0)*1024 + n0;
#pragma unroll
    for (int r = 0; r < 4; r++) tile[ty + r*8][tx] = xp[(size_t)(ty + r*8)*1024 + tx];
    __syncthreads();
#pragma unroll
    for (int r = 0; r < 4; r++) {
        int nl = ty + r*8;
        __nv_bfloat16 h, l; bsplit(tile[tx][nl], h, l);
        size_t o = ((size_t)b*1024 + n0 + nl)*512 + d0 + tx;
        g_xT_hi[o] = h; g_xT_lo[o] = l;
    }
}

// ================= warp-MMA GEMM (NT, K-major operands, K'=3K hi/lo) =================
// CTA tile 128x128, BK=64, 8 warps of 64x32. Output row-major [M][N].
// MODE 0: cv1    M=n(1024) N=c(256)  K=512  A=xT      B=w1    epi BN(col)+SiLU -> x1T
// MODE 1: qke    M=n(1024) N=m'(768) K=256  A=x1T     B=wqke  epi +bias(col)  -> qT/kT/eT
// MODE 2: v      M=c(256)  N=n(1024) K=256  A=wv      B=x1T   epi +bias(row)  -> v
// MODE 3: logits M=i(1024) N=j(1024) K=512  A=qT|posT B=kT|eT               -> logits fp32
// MODE 4: out    M=i(1024) N=c(256)  K=1024 A=attn    B=v                    -> outT
// MODE 5: cv2    M=d(512)  N=n(1024) K=256  A=w2      B=outT  epi BN(row)+SiLU+resid -> d_out
template <int MODE>
__global__ void __launch_bounds__(256)
gemm_mma(const float* __restrict__ p0, const float* __restrict__ p1,
         const float* __restrict__ p2, float* __restrict__ pout) {
    constexpr int K   = (MODE==0 || MODE==3) ? 512 : (MODE==4 ? 1024 : 256);
    constexpr int KIT = K / 64;
    constexpr int NIT = 3 * KIT;
    constexpr int ST  = (MODE==0) ? 512 : (MODE==4 ? 1024 : 256);   // row stride (elems) of both operands

    extern __shared__ char smem[];
    const uint32_t sbase = smem_u32(smem);
    const int tid = threadIdx.x, wid = tid >> 5, lane = tid & 31;
    const int b = blockIdx.z, m0 = blockIdx.y * 128, n0 = blockIdx.x * 128;
    const int warpM = (wid & 1) * 64, warpN = (wid >> 1) * 32;
    const int rsel = lane & 15, csel = lane >> 4, lane7 = lane & 7;

    // per-thread cp.async slots: 128 rows x 64 elems per tile, 4 chunks of 16B per thread
    uint32_t sOff[4]; int rowi[4], qi[4];
#pragma unroll
    for (int c = 0; c < 4; c++) {
        int idx = tid + c*256;
        rowi[c] = idx >> 3; qi[c] = idx & 7;
        sOff[c] = (uint32_t)(rowi[c]*128 + ((qi[c] ^ (rowi[c] & 7)) << 4));
    }

    const __nv_bfloat16 *pa, *pb;
    auto get_ptrs = [&](int it) {
        int phase = it / KIT;
        int kk = (it - phase*KIT) * 64;
        if (MODE == 0) {
            pa = (phase < 2 ? g_xT_hi : g_xT_lo) + ((size_t)b*1024 + m0)*512 + kk;
            pb = (phase == 1 ? g_w1_lo : g_w1_hi) + (size_t)n0*512 + kk;
        } else if (MODE == 1) {
            pa = (phase < 2 ? g_x1T_hi : g_x1T_lo) + ((size_t)b*1024 + m0)*256 + kk;
            pb = (phase == 1 ? g_wqke_lo : g_wqke_hi) + (size_t)n0*256 + kk;
        } else if (MODE == 2) {
            pa = (phase < 2 ? g_wv_hi : g_wv_lo) + (size_t)m0*256 + kk;
            pb = (phase == 1 ? g_x1T_lo : g_x1T_hi) + ((size_t)b*1024 + n0)*256 + kk;
        } else if (MODE == 3) {
            if (kk < 256) {
                pa = (phase < 2 ? g_qT_hi : g_qT_lo) + ((size_t)b*1024 + m0)*256 + kk;
                pb = (phase == 1 ? g_kT_lo : g_kT_hi) + ((size_t)b*1024 + n0)*256 + kk;
            } else {
                pa = (phase < 2 ? g_posT_hi : g_posT_lo) + (size_t)m0*256 + (kk - 256);
                pb = (phase == 1 ? g_eT_lo : g_eT_hi) + ((size_t)b*1024 + n0)*256 + (kk - 256);
            }
        } else if (MODE == 4) {
            pa = (phase < 2 ? g_attn_hi : g_attn_lo) + ((size_t)b*1024 + m0)*1024 + kk;
            pb = (phase == 1 ? g_v_lo : g_v_hi) + ((size_t)b*256 + n0)*1024 + kk;
        } else {
            pa = (phase < 2 ? g_w2_hi : g_w2_lo) + (size_t)m0*256 + kk;
            pb = (phase == 1 ? g_outT_lo : g_outT_hi) + ((size_t)b*1024 + n0)*256 + kk;
        }
    };
    auto issue = [&](int buf) {
        uint32_t sA = sbase + buf*16384;
        uint32_t sB = sbase + 32768 + buf*16384;
#pragma unroll
        for (int c = 0; c < 4; c++) {
            cp16(sA + sOff[c], pa + (size_t)rowi[c]*ST + qi[c]*8);
            cp16(sB + sOff[c], pb + (size_t)rowi[c]*ST + qi[c]*8);
        }
        CP_COMMIT();
    };

    // ldmatrix row byte offsets (iteration-invariant)
    uint32_t rowA[4], rowB[2];
#pragma unroll
    for (int fi = 0; fi < 4; fi++) rowA[fi] = (uint32_t)((warpM + fi*16 + rsel) * 128);
#pragma unroll
    for (int fj = 0; fj < 2; fj++) rowB[fj] = (uint32_t)((warpN + fj*16 + rsel) * 128);

    float acc[4][4][4] = {};

    get_ptrs(0);
    issue(0);
    CP_WAIT0();
    __syncthreads();

    for (int it = 0; it < NIT; ++it) {
        const int s = it & 1;
        if (it + 1 < NIT) { get_ptrs(it + 1); issue(s ^ 1); }
        const uint32_t abase = sbase + s*16384;
        const uint32_t bbase = sbase + 32768 + s*16384;
#pragma unroll
        for (int ks = 0; ks < 4; ++ks) {
            const uint32_t chunk = (uint32_t)(((ks*2 + csel) ^ lane7) << 4);
            uint32_t a[4][4], bq[2][4];
#pragma unroll
            for (int fi = 0; fi < 4; fi++) ldsm4(a[fi], abase + rowA[fi] + chunk);
#pragma unroll
            for (int fj2 = 0; fj2 < 2; fj2++) ldsm4(bq[fj2], bbase + rowB[fj2] + chunk);
#pragma unroll
            for (int fi = 0; fi < 4; fi++)
#pragma unroll
                for (int fj = 0; fj < 4; fj++) {
                    uint32_t bb[2] = { bq[fj >> 1][fj & 1], bq[fj >> 1][2 + (fj & 1)] };
                    mma16816(acc[fi][fj], a[fi], bb);
                }
        }
        if (it + 1 < NIT) CP_WAIT0();
        __syncthreads();
    }

    // ---- epilogue: fragment (r,c): acc[0,1]=rows r, acc[2,3]=rows r+8, cols c,c+1 ----
    const float rs = rsqrtf(1.0f + 1e-5f);
#pragma unroll
    for (int fi = 0; fi < 4; fi++) {
        int r0 = m0 + warpM + fi*16 + (lane >> 2);
#pragma unroll
        for (int fj = 0; fj < 4; fj++) {
            int c = n0 + warpN + fj*8 + (lane & 3)*2;
#pragma unroll
            for (int h = 0; h < 2; h++) {
                int r = r0 + h*8;
                float v0 = acc[fi][fj][h*2], v1 = acc[fi][fj][h*2 + 1];
                if (MODE == 0) {
                    float t0 = fmaf(v0, p0[c]*rs,   p1[c]);
                    float t1 = fmaf(v1, p0[c+1]*rs, p1[c+1]);
                    uint32_t hi2, lo2; split_pair(silu(t0), silu(t1), hi2, lo2);
                    size_t o = ((size_t)b*1024 + r)*256 + c;
                    *reinterpret_cast<uint32_t*>(&g_x1T_hi[o]) = hi2;
                    *reinterpret_cast<uint32_t*>(&g_x1T_lo[o]) = lo2;
                } else if (MODE == 1) {
                    uint32_t hi2, lo2; split_pair(v0 + g_bqke[c], v1 + g_bqke[c+1], hi2, lo2);
                    int sel = c >> 8;
                    size_t o = ((size_t)b*1024 + r)*256 + (c & 255);
                    __nv_bfloat16* dh = (sel==0) ? g_qT_hi : (sel==1) ? g_kT_hi : g_eT_hi;
                    __nv_bfloat16* dl = (sel==0) ? g_qT_lo : (sel==1) ? g_kT_lo : g_eT_lo;
                    *reinterpret_cast<uint32_t*>(&dh[o]) = hi2;
                    *reinterpret_cast<uint32_t*>(&dl[o]) = lo2;
                } else if (MODE == 2) {
                    float bi = g_bv[r];
                    uint32_t hi2, lo2; split_pair(v0 + bi, v1 + bi, hi2, lo2);
                    size_t o = ((size_t)b*256 + r)*1024 + c;
                    *reinterpret_cast<uint32_t*>(&g_v_hi[o]) = hi2;
                    *reinterpret_cast<uint32_t*>(&g_v_lo[o]) = lo2;
                } else if (MODE == 3) {
                    size_t o = ((size_t)b*1024 + r)*1024 + c;
                    float2 f2 = make_float2(v0, v1);
                    *reinterpret_cast<float2*>(&g_logits[o]) = f2;
                } else if (MODE == 4) {
                    uint32_t hi2, lo2; split_pair(v0, v1, hi2, lo2);
                    size_t o = ((size_t)b*1024 + r)*256 + c;
                    *reinterpret_cast<uint32_t*>(&g_outT_hi[o]) = hi2;
                    *reinterpret_cast<uint32_t*>(&g_outT_lo[o]) = lo2;
                } else {
                    float sc = p0[r]*rs, bt = p1[r];
                    size_t o = ((size_t)b*512 + r)*1024 + c;
                    float y0 = silu(fmaf(v0, sc, bt)) + p2[o];
                    float y1 = silu(fmaf(v1, sc, bt)) + p2[o + 1];
                    float2 f2 = make_float2(y0, y1);
                    *reinterpret_cast<float2*>(&pout[o]) = f2;
                }
            }
        }
    }
}

// ================= softmax -> attn hi/lo bf16 =================
__global__ void __launch_bounds__(256)
softmax_k() {
    size_t row = blockIdx.x;
    float* p = g_logits + row * 1024;
    const int tid = threadIdx.x;
    __shared__ float red[8];

    float4 v = *reinterpret_cast<const float4*>(&p[tid*4]);
    float m = fmaxf(fmaxf(v.x, v.y), fmaxf(v.z, v.w));
#pragma unroll
    for (int o = 16; o; o >>= 1) m = fmaxf(m, __shfl_xor_sync(0xffffffffu, m, o));
    if ((tid & 31) == 0) red[tid >> 5] = m;
    __syncthreads();
    m = red[0];
#pragma unroll
    for (int r = 1; r < 8; r++) m = fmaxf(m, red[r]);
    __syncthreads();

    float e0 = __expf(v.x - m), e1 = __expf(v.y - m), e2 = __expf(v.z - m), e3 = __expf(v.w - m);
    float s = (e0 + e1) + (e2 + e3);
#pragma unroll
    for (int o = 16; o; o >>= 1) s += __shfl_xor_sync(0xffffffffu, s, o);
    if ((tid & 31) == 0) red[tid >> 5] = s;
    __syncthreads();
    s = ((red[0]+red[1]) + (red[2]+red[3])) + ((red[4]+red[5]) + (red[6]+red[7]));
    float inv = 1.0f / s;
    uint32_t h2, l2;
    split_pair(e0*inv, e1*inv, h2, l2);
    size_t o = row*1024 + tid*4;
    *reinterpret_cast<uint32_t*>(&g_attn_hi[o]) = h2;
    *reinterpret_cast<uint32_t*>(&g_attn_lo[o]) = l2;
    split_pair(e2*inv, e3*inv, h2, l2);
    *reinterpret_cast<uint32_t*>(&g_attn_hi[o + 2]) = h2;
    *reinterpret_cast<uint32_t*>(&g_attn_lo[o + 2]) = l2;
}

#define SMEM_BYTES 65536

// ================= launch =================
extern "C" void kernel_launch(void* const* d_in, const int* in_sizes, int n_in,
                              void* d_out, int out_size) {
    const float* x     = (const float*)d_in[0];
    const float* cv1_w = (const float*)d_in[1];
    const float* cv1_g = (const float*)d_in[2];
    const float* cv1_b = (const float*)d_in[3];
    const float* q_w   = (const float*)d_in[4];
    const float* q_b   = (const float*)d_in[5];
    const float* k_w   = (const float*)d_in[6];
    const float* k_b   = (const float*)d_in[7];
    const float* v_w   = (const float*)d_in[8];
    const float* v_b   = (const float*)d_in[9];
    const float* e_w   = (const float*)d_in[10];
    const float* e_b   = (const float*)d_in[11];
    const float* rel_h = (const float*)d_in[12];
    const float* rel_w = (const float*)d_in[13];
    const float* cv2_w = (const float*)d_in[14];
    const float* cv2_g = (const float*)d_in[15];
    const float* cv2_b = (const float*)d_in[16];
    float* out = (float*)d_out;

    cudaFuncSetAttribute(gemm_mma<0>, cudaFuncAttributeMaxDynamicSharedMemorySize, SMEM_BYTES);
    cudaFuncSetAttribute(gemm_mma<1>, cudaFuncAttributeMaxDynamicSharedMemorySize, SMEM_BYTES);
    cudaFuncSetAttribute(gemm_mma<2>, cudaFuncAttributeMaxDynamicSharedMemorySize, SMEM_BYTES);
    cudaFuncSetAttribute(gemm_mma<3>, cudaFuncAttributeMaxDynamicSharedMemorySize, SMEM_BYTES);
    cudaFuncSetAttribute(gemm_mma<4>, cudaFuncAttributeMaxDynamicSharedMemorySize, SMEM_BYTES);
    cudaFuncSetAttribute(gemm_mma<5>, cudaFuncAttributeMaxDynamicSharedMemorySize, SMEM_BYTES);

    prep_w<<<1024, 256>>>(cv1_w, q_w, k_w, v_w, e_w, q_b, k_b, v_b, e_b, cv2_w, rel_h, rel_w);
    xt_conv<<<dim3(32, 16, BATCH), dim3(32, 8)>>>(x);

    // cv1: x1T[n][c] = silu(bn(xT @ W1^T))
    gemm_mma<0><<<dim3(2, 8, BATCH), 256, SMEM_BYTES>>>(cv1_g, cv1_b, nullptr, nullptr);
    // q/k/e: [n][768] -> qT,kT,eT
    gemm_mma<1><<<dim3(6, 8, BATCH), 256, SMEM_BYTES>>>(nullptr, nullptr, nullptr, nullptr);
    // v: [c][n]
    gemm_mma<2><<<dim3(8, 2, BATCH), 256, SMEM_BYTES>>>(nullptr, nullptr, nullptr, nullptr);
    // logits[i][j] = q.k + pos.e
    gemm_mma<3><<<dim3(8, 8, BATCH), 256, SMEM_BYTES>>>(nullptr, nullptr, nullptr, nullptr);
    // softmax + bf16 split
    softmax_k<<<BATCH * 1024, 256>>>();
    // outT[i][c] = attn @ v^T
    gemm_mma<4><<<dim3(2, 8, BATCH), 256, SMEM_BYTES>>>(nullptr, nullptr, nullptr, nullptr);
    // cv2: y[d][n] = x + silu(bn(W2 @ out))
    gemm_mma<5><<<dim3(8, 4, BATCH), 256, SMEM_BYTES>>>(cv2_g, cv2_b, x, out);
}